// round 15
// baseline (speedup 1.0000x reference)
#include <cuda_runtime.h>
#include <cstdint>
#include <math.h>

// Problem constants
#define Dm   512
#define Hn   8
#define DH   64
#define NBLK 6
#define Vv   32000
#define Ff   2048
#define Bb   2
#define Ll   1024
#define NTOK (Bb * Ll)   // 2048

// ---------------------------------------------------------------------------
// Scratch (device globals; no allocation allowed)
// ---------------------------------------------------------------------------
__device__ float g_h [NTOK * Dm];
__device__ float g_y [NTOK * Dm];
__device__ float g_q [NTOK * Dm];
__device__ float g_k [NTOK * Dm];
__device__ float g_v [NTOK * Dm];
__device__ float g_o [NTOK * Dm];
__device__ float g_ff[NTOK * Ff];
__device__ float g_ctx[NTOK * Dm];          // tf32-rounded ctx
__device__ float g_embt[(size_t)Vv * Dm];   // tf32-rounded emb (logits B)

// Transposed (and tf32-rounded) weights per block:
// 8 x [512x512] + w1T [2048x512] + w2T [512x2048]
#define WBLK_STRIDE 4194304ull
#define W1T_OFF     2097152ull
#define W2T_OFF     3145728ull
__device__ float g_wt[NBLK * WBLK_STRIDE];

// ---------------------------------------------------------------------------
// Portable PTX helpers (sm_80+ baseline ISA, valid on compute_103)
// ---------------------------------------------------------------------------
__device__ __forceinline__ uint32_t s2u(const void* p) {
    uint32_t a;
    asm("{ .reg .u64 t; cvta.to.shared.u64 t, %1; cvt.u32.u64 %0, t; }"
        : "=r"(a) : "l"(p));
    return a;
}

__device__ __forceinline__ float tfr(float f) {   // round-to-nearest tf32
    uint32_t u;
    asm("cvt.rna.tf32.f32 %0, %1;" : "=r"(u) : "f"(f));
    return __uint_as_float(u);
}

__device__ __forceinline__ void cpa16(uint32_t dst, const void* src) {
    asm volatile("cp.async.cg.shared.global [%0], [%1], 16;"
                 :: "r"(dst), "l"(src));
}

#define CP_COMMIT() asm volatile("cp.async.commit_group;")
#define CP_WAIT1()  asm volatile("cp.async.wait_group 1;")

__device__ __forceinline__ void mma_tf32(float c[4], const uint32_t a[4],
                                         const uint32_t b[2]) {
    asm volatile(
        "mma.sync.aligned.m16n8k8.row.col.f32.tf32.tf32.f32 "
        "{%0,%1,%2,%3}, {%4,%5,%6,%7}, {%8,%9}, {%0,%1,%2,%3};"
        : "+f"(c[0]), "+f"(c[1]), "+f"(c[2]), "+f"(c[3])
        : "r"(a[0]), "r"(a[1]), "r"(a[2]), "r"(a[3]),
          "r"(b[0]), "r"(b[1]));
}

// ---------------------------------------------------------------------------
// TF32 GEMM: C[M,N] = A[M,K] @ BT[N,K]^T  (+bias)(+relu)(+res)(+rnd-out)
// All operands PRE-ROUNDED to tf32 -> zero cvts in mainloop.
// CTA tile 64x128, BK=32, 256 threads = 2(m) x 4(n) warps, warp tile 32x32.
// 3-stage cp.async pipeline, ONE __syncthreads per chunk.
// Requires M%64==0, N%128==0, K%32==0, K>=64.
// ---------------------------------------------------------------------------
#define BKC  32
#define SSTR 36                   // smem row stride in words (bank-safe)
#define AW   (64 * SSTR)          // words per A stage
#define BW   (128 * SSTR)         // words per B stage
#define STW  (AW + BW)            // words per stage
#define SMB  (3 * STW * 4)        // 82944 bytes

template <bool BIAS, bool RELU, bool RES, bool RND>
__global__ void __launch_bounds__(256, 2)
mm_gemm(const float* __restrict__ A, const float* __restrict__ BT,
        const float* __restrict__ bias, const float* __restrict__ res,
        float* __restrict__ C, int M, int N, int K) {
    extern __shared__ uint32_t smem[];
    uint32_t sbase = s2u(smem);

    int tid = threadIdx.x;
    int w = tid >> 5, lane = tid & 31;
    int g = lane >> 2, t4 = lane & 3;
    int wm = w >> 2, wn = w & 3;            // 2 x 4 warp grid
    int n0 = blockIdx.x * 128, m0 = blockIdx.y * 64;

    float acc[2][4][4];
#pragma unroll
    for (int mt = 0; mt < 2; mt++)
#pragma unroll
        for (int nt = 0; nt < 4; nt++)
#pragma unroll
            for (int i = 0; i < 4; i++) acc[mt][nt][i] = 0.f;

    // staging maps:
    // A: 64 rows x 8 float4 = 512 slots, 2/thread
    // B: 128 rows x 8 float4 = 1024 slots, 4/thread
    int lrowA = tid >> 2;
    int baseA = (tid & 3) * 2;              // float4 slot (0,2,4,6)
    int lrowB = tid >> 1;
    int baseB = (tid & 1) * 4;              // float4 slot (0 or 4)

    const float* Agp = A  + (size_t)(m0 + lrowA) * K + (baseA << 2);
    const float* Bgp = BT + (size_t)(n0 + lrowB) * K + (baseB << 2);
    uint32_t aS0 = sbase + (uint32_t)(lrowA * SSTR + baseA * 4) * 4;
    uint32_t bS0 = sbase + (uint32_t)(AW + lrowB * SSTR + baseB * 4) * 4;

    int nch = K >> 5;

    // prologue: chunk 0 -> stage 0, chunk 1 -> stage 1
#pragma unroll
    for (int p = 0; p < 2; p++) {
        uint32_t so = (uint32_t)p * (STW * 4);
        cpa16(aS0 + so,      Agp + p * BKC);
        cpa16(aS0 + so + 16, Agp + p * BKC + 4);
        cpa16(bS0 + so,      Bgp + p * BKC);
        cpa16(bS0 + so + 16, Bgp + p * BKC + 4);
        cpa16(bS0 + so + 32, Bgp + p * BKC + 8);
        cpa16(bS0 + so + 48, Bgp + p * BKC + 12);
        CP_COMMIT();
    }

    for (int c = 0; c < nch; c++) {
        CP_WAIT1();
        __syncthreads();
        if (c + 2 < nch) {
            int st = (c + 2) % 3;
            uint32_t so = (uint32_t)st * (STW * 4);
            const float* Ag2 = Agp + (c + 2) * BKC;
            const float* Bg2 = Bgp + (c + 2) * BKC;
            cpa16(aS0 + so,      Ag2);
            cpa16(aS0 + so + 16, Ag2 + 4);
            cpa16(bS0 + so,      Bg2);
            cpa16(bS0 + so + 16, Bg2 + 4);
            cpa16(bS0 + so + 32, Bg2 + 8);
            cpa16(bS0 + so + 48, Bg2 + 12);
        }
        CP_COMMIT();

        const uint32_t* Abuf = smem + (c % 3) * STW;
        const uint32_t* Bbuf = Abuf + AW;
#pragma unroll
        for (int k8 = 0; k8 < BKC / 8; k8++) {
            int kk = (k8 << 3) + t4;
            uint32_t af[2][4];
#pragma unroll
            for (int mt = 0; mt < 2; mt++) {
                const uint32_t* ap = Abuf + (wm * 32 + mt * 16 + g) * SSTR + kk;
                af[mt][0] = ap[0];
                af[mt][1] = ap[8 * SSTR];
                af[mt][2] = ap[4];
                af[mt][3] = ap[8 * SSTR + 4];
            }
            uint32_t bf[4][2];
#pragma unroll
            for (int nt = 0; nt < 4; nt++) {
                const uint32_t* bp = Bbuf + (wn * 32 + nt * 8 + g) * SSTR + kk;
                bf[nt][0] = bp[0];
                bf[nt][1] = bp[4];
            }
#pragma unroll
            for (int mt = 0; mt < 2; mt++)
#pragma unroll
                for (int nt = 0; nt < 4; nt++)
                    mma_tf32(acc[mt][nt], af[mt], bf[nt]);
        }
    }

    // epilogue
#pragma unroll
    for (int mt = 0; mt < 2; mt++) {
        int r0 = m0 + wm * 32 + mt * 16 + g;
#pragma unroll
        for (int nt = 0; nt < 4; nt++) {
            int cc = n0 + wn * 32 + nt * 8 + t4 * 2;
            float2 v0 = make_float2(acc[mt][nt][0], acc[mt][nt][1]);
            float2 v1 = make_float2(acc[mt][nt][2], acc[mt][nt][3]);
            if (BIAS) {
                float2 bb = *(const float2*)(bias + cc);
                v0.x += bb.x; v0.y += bb.y; v1.x += bb.x; v1.y += bb.y;
            }
            if (RELU) {
                v0.x = fmaxf(v0.x, 0.f); v0.y = fmaxf(v0.y, 0.f);
                v1.x = fmaxf(v1.x, 0.f); v1.y = fmaxf(v1.y, 0.f);
            }
            if (RES) {
                float2 r4 = *(const float2*)(res + (size_t)r0 * N + cc);
                v0.x += r4.x; v0.y += r4.y;
                float2 r5 = *(const float2*)(res + (size_t)(r0 + 8) * N + cc);
                v1.x += r5.x; v1.y += r5.y;
            }
            if (RND) {
                v0.x = tfr(v0.x); v0.y = tfr(v0.y);
                v1.x = tfr(v1.x); v1.y = tfr(v1.y);
            }
            *(float2*)(C + (size_t)r0 * N + cc) = v0;
            *(float2*)(C + (size_t)(r0 + 8) * N + cc) = v1;
        }
    }
}

template <bool BIAS, bool RELU, bool RES, bool RND>
static inline void tgemm(const float* A, const float* BT, const float* bias,
                         const float* res, float* C, int M, int N, int K) {
    cudaFuncSetAttribute(mm_gemm<BIAS, RELU, RES, RND>,
                         cudaFuncAttributeMaxDynamicSharedMemorySize, SMB);
    dim3 grid(N / 128, M / 64);
    mm_gemm<BIAS, RELU, RES, RND><<<grid, 256, SMB>>>(A, BT, bias, res, C, M, N, K);
}

// ---------------------------------------------------------------------------
// Weight transpose ([K,N] -> [N,K]) with tf32 rounding at the write
// ---------------------------------------------------------------------------
struct P8 { const float* p[8]; };

__global__ void trans_dd(P8 s, float* dst) {
    __shared__ float t[32][33];
    int z = blockIdx.z;
    int kd = z / 6, i = z - kd * 6;
    const float* src = s.p[kd] + (size_t)i * 262144;
    float* d = dst + (size_t)i * WBLK_STRIDE + (size_t)kd * 262144;
    int tx = threadIdx.x, ty = threadIdx.y;
    int x = blockIdx.x * 32 + tx;
    int y0 = blockIdx.y * 32;
#pragma unroll
    for (int r = 0; r < 32; r += 8)
        t[ty + r][tx] = src[(size_t)(y0 + ty + r) * 512 + x];
    __syncthreads();
    int x2 = y0 + tx;
    int y2 = blockIdx.x * 32;
#pragma unroll
    for (int r = 0; r < 32; r += 8)
        d[(size_t)(y2 + ty + r) * 512 + x2] = tfr(t[tx][ty + r]);
}

__global__ void trans_rc(const float* __restrict__ src, float* __restrict__ dst,
                         int R, int C, size_t dOff) {
    __shared__ float t[32][33];
    const float* s = src + (size_t)blockIdx.z * R * C;
    float* d = dst + (size_t)blockIdx.z * WBLK_STRIDE + dOff;
    int tx = threadIdx.x, ty = threadIdx.y;
    int x = blockIdx.x * 32 + tx;
    int y0 = blockIdx.y * 32;
#pragma unroll
    for (int r = 0; r < 32; r += 8)
        t[ty + r][tx] = s[(size_t)(y0 + ty + r) * C + x];
    __syncthreads();
    int x2 = y0 + tx;
    int y2 = blockIdx.x * 32;
#pragma unroll
    for (int r = 0; r < 32; r += 8)
        d[(size_t)(y2 + ty + r) * R + x2] = tfr(t[tx][ty + r]);
}

// Rounded copy (float4 granularity)
__global__ void cvt_round(const float* __restrict__ src, float* __restrict__ dst,
                          int n4) {
    int i = blockIdx.x * 256 + threadIdx.x;
    if (i < n4) {
        float4 v = ((const float4*)src)[i];
        v.x = tfr(v.x); v.y = tfr(v.y); v.z = tfr(v.z); v.w = tfr(v.w);
        ((float4*)dst)[i] = v;
    }
}

// ---------------------------------------------------------------------------
// Embedding * sqrt(D) + sinusoidal positional encoding (full fp32 h)
// ---------------------------------------------------------------------------
__global__ void embed_kernel(const int* __restrict__ x,
                             const float* __restrict__ emb,
                             float* __restrict__ h) {
    int n = blockIdx.x;
    int l = n & (Ll - 1);
    int tok = x[n];
    int d0 = threadIdx.x * 4;
#pragma unroll
    for (int u = 0; u < 4; u++) {
        int d = d0 + u;
        int i = (d < 256) ? d : d - 256;
        float denom = powf(10000.0f, (float)i * (1.0f / 256.0f));
        float ang = (float)l / denom;
        float pos = (d < 256) ? sinf(ang) : cosf(ang);
        h[(size_t)n * Dm + d] = emb[(size_t)tok * Dm + d] * 22.62741699796952f + pos;
    }
}

// ---------------------------------------------------------------------------
// LayerNorm, output tf32-rounded (only ever consumed as GEMM A-operand)
// ---------------------------------------------------------------------------
__global__ void ln_kernel(const float* __restrict__ x,
                          const float* __restrict__ gw,
                          const float* __restrict__ bw,
                          float* __restrict__ y) {
    int row = blockIdx.x;
    int t = threadIdx.x;
    float4 xv = ((const float4*)(x + (size_t)row * Dm))[t];
    float s  = xv.x + xv.y + xv.z + xv.w;
    float ss = xv.x * xv.x + xv.y * xv.y + xv.z * xv.z + xv.w * xv.w;
#pragma unroll
    for (int o = 16; o > 0; o >>= 1) {
        s  += __shfl_xor_sync(0xFFFFFFFFu, s, o);
        ss += __shfl_xor_sync(0xFFFFFFFFu, ss, o);
    }
    __shared__ float sh_s[4], sh_ss[4];
    int w = t >> 5, lane = t & 31;
    if (lane == 0) { sh_s[w] = s; sh_ss[w] = ss; }
    __syncthreads();
    s  = sh_s[0] + sh_s[1] + sh_s[2] + sh_s[3];
    ss = sh_ss[0] + sh_ss[1] + sh_ss[2] + sh_ss[3];
    float mean = s * (1.0f / Dm);
    float var  = ss * (1.0f / Dm) - mean * mean;
    float inv = rsqrtf(var + 1e-6f);
    float4 gv = ((const float4*)gw)[t];
    float4 bv = ((const float4*)bw)[t];
    float4 ov;
    ov.x = tfr((xv.x - mean) * inv * gv.x + bv.x);
    ov.y = tfr((xv.y - mean) * inv * gv.y + bv.y);
    ov.z = tfr((xv.z - mean) * inv * gv.z + bv.z);
    ov.w = tfr((xv.w - mean) * inv * gv.w + bv.w);
    ((float4*)(y + (size_t)row * Dm))[t] = ov;
}

// ---------------------------------------------------------------------------
// Fused flash-style attention (fp32 math, tf32-rounded output).
// q-tile 32, 128 threads: 4 threads per query (quad owns 16 of 64 dims each).
// Score reduced across the quad via 2x shfl. The j-loop trip count is
// WARP-UNIFORM (computed from the warp's max query); per-lane causality is
// handled by predicating the m/lsum/ov update. This keeps the full-mask
// shfl collective deadlock-free under causal masking.
// Grid (32, 8, 2) = 512 CTAs.
// ---------------------------------------------------------------------------
template <bool CAUSAL>
__global__ void __launch_bounds__(128)
attn_kernel(const float* __restrict__ Q, const float* __restrict__ K,
            const float* __restrict__ V, float* __restrict__ O) {
    __shared__ float Ks[64][64];
    __shared__ float Vs[64][64];
    int t = threadIdx.x;
    int qt = blockIdx.x, hh = blockIdx.y, b = blockIdx.z;
    int qidx = t >> 2, part = t & 3;
    int q = qt * 32 + qidx;
    int qwmax = qt * 32 + ((t >> 5) << 3) + 7;   // max query in this warp

    const float* qptr = Q + ((size_t)(b * Ll + q)) * Dm + hh * DH + part * 16;
    float4 qv[4];
#pragma unroll
    for (int d = 0; d < 4; d++) qv[d] = ((const float4*)qptr)[d];
    float4 ov[4];
#pragma unroll
    for (int d = 0; d < 4; d++) ov[d] = make_float4(0.f, 0.f, 0.f, 0.f);
    float m = -1e30f, lsum = 0.f;

    int kmax = CAUSAL ? (qt * 32 + 32) : Ll;
    for (int k0 = 0; k0 < kmax; k0 += 64) {
#pragma unroll
        for (int it = 0; it < 8; it++) {
            int idx = t + it * 128;      // 0..1023 float4 slots
            int r = idx >> 4;            // 0..63
            int c = (idx & 15) << 2;     // 0..60
            size_t off = ((size_t)(b * Ll + k0 + r)) * Dm + hh * DH + c;
            *(float4*)&Ks[r][c] = *(const float4*)(K + off);
            *(float4*)&Vs[r][c] = *(const float4*)(V + off);
        }
        __syncthreads();
        // warp-uniform trip count; per-lane causal masking via predicate
        int jend = 64;
        if (CAUSAL) {
            int lim = qwmax - k0 + 1;
            jend = lim < 64 ? (lim < 0 ? 0 : lim) : 64;
        }
        for (int j = 0; j < jend; j++) {
            const float4* kr = (const float4*)&Ks[j][part * 16];
            float s = 0.f;
#pragma unroll
            for (int d = 0; d < 4; d++) {
                float4 kv = kr[d];
                s += qv[d].x * kv.x + qv[d].y * kv.y + qv[d].z * kv.z + qv[d].w * kv.w;
            }
            s += __shfl_xor_sync(0xFFFFFFFFu, s, 1);
            s += __shfl_xor_sync(0xFFFFFFFFu, s, 2);
            bool ok = !CAUSAL || (k0 + j <= q);
            if (ok) {
                s *= 0.125f;   // 1/sqrt(64)
                float mn = fmaxf(m, s);
                float cf = __expf(m - mn);
                float p = __expf(s - mn);
                m = mn;
                lsum = lsum * cf + p;
                const float4* vr = (const float4*)&Vs[j][part * 16];
#pragma unroll
                for (int d = 0; d < 4; d++) {
                    float4 vvv = vr[d];
                    ov[d].x = ov[d].x * cf + p * vvv.x;
                    ov[d].y = ov[d].y * cf + p * vvv.y;
                    ov[d].z = ov[d].z * cf + p * vvv.z;
                    ov[d].w = ov[d].w * cf + p * vvv.w;
                }
            }
        }
        __syncthreads();
    }
    float inv = 1.0f / lsum;
    float* optr = O + ((size_t)(b * Ll + q)) * Dm + hh * DH + part * 16;
#pragma unroll
    for (int d = 0; d < 4; d++) {
        float4 r = ov[d];
        r.x = tfr(r.x * inv); r.y = tfr(r.y * inv);
        r.z = tfr(r.z * inv); r.w = tfr(r.w * inv);
        ((float4*)optr)[d] = r;
    }
}

// ---------------------------------------------------------------------------
// kernel_launch
// ---------------------------------------------------------------------------
extern "C" void kernel_launch(void* const* d_in, const int* in_sizes, int n_in,
                              void* d_out, int out_size) {
    const int*   x     = (const int*)  d_in[0];
    const float* ctx   = (const float*)d_in[1];
    const float* emb   = (const float*)d_in[2];
    const float* wq_s  = (const float*)d_in[3];
    const float* wk_s  = (const float*)d_in[4];
    const float* wv_s  = (const float*)d_in[5];
    const float* wo_s  = (const float*)d_in[6];
    const float* wq_c  = (const float*)d_in[7];
    const float* wk_c  = (const float*)d_in[8];
    const float* wv_c  = (const float*)d_in[9];
    const float* wo_c  = (const float*)d_in[10];
    const float* w1    = (const float*)d_in[11];
    const float* b1    = (const float*)d_in[12];
    const float* w2    = (const float*)d_in[13];
    const float* b2    = (const float*)d_in[14];
    const float* ln1_g = (const float*)d_in[15];
    const float* ln1_b = (const float*)d_in[16];
    const float* ln2_g = (const float*)d_in[17];
    const float* ln2_b = (const float*)d_in[18];
    const float* ln3_g = (const float*)d_in[19];
    const float* ln3_b = (const float*)d_in[20];
    const float* lnf_g = (const float*)d_in[21];
    const float* lnf_b = (const float*)d_in[22];
    float* out = (float*)d_out;

    float *h, *y, *q, *k, *v, *o, *ff, *wt, *ctxr, *embt;
    cudaGetSymbolAddress((void**)&h,    g_h);
    cudaGetSymbolAddress((void**)&y,    g_y);
    cudaGetSymbolAddress((void**)&q,    g_q);
    cudaGetSymbolAddress((void**)&k,    g_k);
    cudaGetSymbolAddress((void**)&v,    g_v);
    cudaGetSymbolAddress((void**)&o,    g_o);
    cudaGetSymbolAddress((void**)&ff,   g_ff);
    cudaGetSymbolAddress((void**)&wt,   g_wt);
    cudaGetSymbolAddress((void**)&ctxr, g_ctx);
    cudaGetSymbolAddress((void**)&embt, g_embt);

    // ---- prep: transpose+round weights, round ctx and emb ----
    P8 p8;
    p8.p[0] = wq_s; p8.p[1] = wk_s; p8.p[2] = wv_s; p8.p[3] = wo_s;
    p8.p[4] = wq_c; p8.p[5] = wk_c; p8.p[6] = wv_c; p8.p[7] = wo_c;
    trans_dd<<<dim3(16, 16, 48), dim3(32, 8)>>>(p8, wt);
    trans_rc<<<dim3(64, 16, 6), dim3(32, 8)>>>(w1, wt, 512, 2048, W1T_OFF);
    trans_rc<<<dim3(16, 64, 6), dim3(32, 8)>>>(w2, wt, 2048, 512, W2T_OFF);
    cvt_round<<<(NTOK * Dm / 4 + 255) / 256, 256>>>(ctx, ctxr, NTOK * Dm / 4);
    cvt_round<<<((int)((size_t)Vv * Dm / 4) + 255) / 256, 256>>>(emb, embt,
                                                                 (int)((size_t)Vv * Dm / 4));

    embed_kernel<<<NTOK, 128>>>(x, emb, h);

    dim3 agrid(Ll / 32, Hn, Bb);

    for (int i = 0; i < NBLK; i++) {
        const float* WT = wt + (size_t)i * WBLK_STRIDE;
        // --- self attention ---
        ln_kernel<<<NTOK, 128>>>(h, ln1_g + i * Dm, ln1_b + i * Dm, y);
        tgemm<false, false, false, false>(y, WT + 0 * 262144ull, nullptr, nullptr, q, NTOK, Dm, Dm);
        tgemm<false, false, false, false>(y, WT + 1 * 262144ull, nullptr, nullptr, k, NTOK, Dm, Dm);
        tgemm<false, false, false, false>(y, WT + 2 * 262144ull, nullptr, nullptr, v, NTOK, Dm, Dm);
        attn_kernel<true><<<agrid, 128>>>(q, k, v, o);
        tgemm<false, false, true, false>(o, WT + 3 * 262144ull, nullptr, h, h, NTOK, Dm, Dm);

        // --- cross attention ---
        ln_kernel<<<NTOK, 128>>>(h, ln2_g + i * Dm, ln2_b + i * Dm, y);
        tgemm<false, false, false, false>(y,    WT + 4 * 262144ull, nullptr, nullptr, q, NTOK, Dm, Dm);
        tgemm<false, false, false, false>(ctxr, WT + 5 * 262144ull, nullptr, nullptr, k, NTOK, Dm, Dm);
        tgemm<false, false, false, false>(ctxr, WT + 6 * 262144ull, nullptr, nullptr, v, NTOK, Dm, Dm);
        attn_kernel<false><<<agrid, 128>>>(q, k, v, o);
        tgemm<false, false, true, false>(o, WT + 7 * 262144ull, nullptr, h, h, NTOK, Dm, Dm);

        // --- FFN ---  (FFN1 output rounded: it is FFN2's A operand)
        ln_kernel<<<NTOK, 128>>>(h, ln3_g + i * Dm, ln3_b + i * Dm, y);
        tgemm<true, true, false, true>(y,  WT + W1T_OFF, b1 + (size_t)i * Ff, nullptr, ff, NTOK, Ff, Dm);
        tgemm<true, false, true, false>(ff, WT + W2T_OFF, b2 + (size_t)i * Dm, h, h, NTOK, Dm, Ff);
    }

    // --- final LN + logits = y @ embt^T ---
    ln_kernel<<<NTOK, 128>>>(h, lnf_g, lnf_b, y);
    tgemm<false, false, false, false>(y, embt, nullptr, nullptr, out, NTOK, Vv, Dm);
}

// round 16
// speedup vs baseline: 1.8016x; 1.8016x over previous
#include <cuda_runtime.h>
#include <cuda_fp16.h>
#include <cstdint>
#include <math.h>

// Problem constants
#define Dm   512
#define Hn   8
#define DH   64
#define NBLK 6
#define Vv   32000
#define Ff   2048
#define Bb   2
#define Ll   1024
#define NTOK (Bb * Ll)   // 2048

// ---------------------------------------------------------------------------
// Scratch (device globals; no allocation allowed)
// ---------------------------------------------------------------------------
__device__ float  g_h [NTOK * Dm];            // residual stream (fp32)
__device__ __half g_y [NTOK * Dm];            // LN output (GEMM A)
__device__ __half g_q [NTOK * Dm];
__device__ __half g_k [NTOK * Dm];
__device__ __half g_v [NTOK * Dm];
__device__ __half g_o [NTOK * Dm];
__device__ __half g_ff[NTOK * Ff];
__device__ __half g_ctx[NTOK * Dm];           // fp16 ctx
__device__ __half g_embt[(size_t)Vv * Dm];    // fp16 emb (logits B)

// Transposed fp16 weights per block: 8 x [512x512] + w1T [2048x512] + w2T [512x2048]
#define WBLK_STRIDE 4194304ull
#define W1T_OFF     2097152ull
#define W2T_OFF     3145728ull
__device__ __half g_wt[NBLK * WBLK_STRIDE];

// ---------------------------------------------------------------------------
// Portable PTX helpers (sm_80+ baseline ISA, valid on compute_103)
// ---------------------------------------------------------------------------
__device__ __forceinline__ uint32_t s2u(const void* p) {
    uint32_t a;
    asm("{ .reg .u64 t; cvta.to.shared.u64 t, %1; cvt.u32.u64 %0, t; }"
        : "=r"(a) : "l"(p));
    return a;
}

__device__ __forceinline__ void cpa16(uint32_t dst, const void* src) {
    asm volatile("cp.async.cg.shared.global [%0], [%1], 16;"
                 :: "r"(dst), "l"(src));
}

#define CP_COMMIT() asm volatile("cp.async.commit_group;")
#define CP_WAIT1()  asm volatile("cp.async.wait_group 1;")

__device__ __forceinline__ void mma_f16(float c[4], const uint32_t a[4],
                                        const uint32_t b[2]) {
    asm volatile(
        "mma.sync.aligned.m16n8k16.row.col.f32.f16.f16.f32 "
        "{%0,%1,%2,%3}, {%4,%5,%6,%7}, {%8,%9}, {%0,%1,%2,%3};"
        : "+f"(c[0]), "+f"(c[1]), "+f"(c[2]), "+f"(c[3])
        : "r"(a[0]), "r"(a[1]), "r"(a[2]), "r"(a[3]),
          "r"(b[0]), "r"(b[1]));
}

// ---------------------------------------------------------------------------
// FP16 GEMM: C[M,N] = A[M,K] @ BT[N,K]^T  (+bias)(+relu)(+res) -> fp32 or fp16
// CTA tile 64x128, BK=32, 256 threads = 2(m) x 4(n) warps, warp tile 32x32.
// 3-stage cp.async pipeline, one __syncthreads per chunk.
// Smem rows = 32 halfs = 16 b32, stride 20 b32 -> conflict-free fragments.
// Requires M%64==0, N%128==0, K%32==0, K>=64.
// ---------------------------------------------------------------------------
#define BKC    32                   // K per chunk (halfs)
#define SSTR32 20                   // smem row stride in b32 words
#define AWR    (64 * SSTR32)        // 1280 b32 per A stage
#define BWR    (128 * SSTR32)       // 2560 b32 per B stage
#define STW    (AWR + BWR)          // 3840 b32 per stage
#define SMB    (3 * STW * 4)        // 46080 bytes

template <bool BIAS, bool RELU, bool RES, bool HC>
__global__ void __launch_bounds__(256, 2)
mm_gemm(const __half* __restrict__ A, const __half* __restrict__ BT,
        const float* __restrict__ bias, const float* __restrict__ res,
        void* __restrict__ Cv, int M, int N, int K) {
    extern __shared__ uint32_t smem[];
    uint32_t sbase = s2u(smem);

    int tid = threadIdx.x;
    int w = tid >> 5, lane = tid & 31;
    int g = lane >> 2, t4 = lane & 3;
    int wm = w >> 2, wn = w & 3;            // 2 x 4 warp grid
    int n0 = blockIdx.x * 128, m0 = blockIdx.y * 64;

    float acc[2][4][4];
#pragma unroll
    for (int mt = 0; mt < 2; mt++)
#pragma unroll
        for (int nt = 0; nt < 4; nt++)
#pragma unroll
            for (int i = 0; i < 4; i++) acc[mt][nt][i] = 0.f;

    // staging: A 64 rows x 4 (16B segs) = 256 slots, 1/thread
    //          B 128 rows x 4 segs     = 512 slots, 2/thread (segs segB, segB+1)
    int rowA = tid >> 2, segA = tid & 3;
    int rowB = tid >> 1, segB = (tid & 1) * 2;

    const __half* Agp = A  + (size_t)(m0 + rowA) * K + segA * 8;
    const __half* Bgp = BT + (size_t)(n0 + rowB) * K + segB * 8;
    uint32_t aS0 = sbase + (uint32_t)(rowA * SSTR32 + segA * 4) * 4;
    uint32_t bS0 = sbase + (uint32_t)(AWR + rowB * SSTR32 + segB * 4) * 4;

    int nch = K >> 5;

    // prologue: chunk 0 -> stage 0, chunk 1 -> stage 1
#pragma unroll
    for (int p = 0; p < 2; p++) {
        uint32_t so = (uint32_t)p * (STW * 4);
        cpa16(aS0 + so,      Agp + p * BKC);
        cpa16(bS0 + so,      Bgp + p * BKC);
        cpa16(bS0 + so + 16, Bgp + p * BKC + 8);
        CP_COMMIT();
    }

    for (int c = 0; c < nch; c++) {
        CP_WAIT1();
        __syncthreads();
        if (c + 2 < nch) {
            int st = (c + 2) % 3;
            uint32_t so = (uint32_t)st * (STW * 4);
            const __half* Ag2 = Agp + (c + 2) * BKC;
            const __half* Bg2 = Bgp + (c + 2) * BKC;
            cpa16(aS0 + so,      Ag2);
            cpa16(bS0 + so,      Bg2);
            cpa16(bS0 + so + 16, Bg2 + 8);
        }
        CP_COMMIT();

        const uint32_t* Abuf = smem + (c % 3) * STW;
        const uint32_t* Bbuf = Abuf + AWR;
#pragma unroll
        for (int ks = 0; ks < 2; ks++) {
            int off = (ks << 3) + t4;
            uint32_t af[2][4];
#pragma unroll
            for (int mt = 0; mt < 2; mt++) {
                const uint32_t* ap = Abuf + (wm * 32 + mt * 16 + g) * SSTR32 + off;
                af[mt][0] = ap[0];
                af[mt][1] = ap[8 * SSTR32];
                af[mt][2] = ap[4];
                af[mt][3] = ap[8 * SSTR32 + 4];
            }
            uint32_t bf[4][2];
#pragma unroll
            for (int nt = 0; nt < 4; nt++) {
                const uint32_t* bp = Bbuf + (wn * 32 + nt * 8 + g) * SSTR32 + off;
                bf[nt][0] = bp[0];
                bf[nt][1] = bp[4];
            }
#pragma unroll
            for (int mt = 0; mt < 2; mt++)
#pragma unroll
                for (int nt = 0; nt < 4; nt++)
                    mma_f16(acc[mt][nt], af[mt], bf[nt]);
        }
    }

    // epilogue
#pragma unroll
    for (int mt = 0; mt < 2; mt++) {
        int r0 = m0 + wm * 32 + mt * 16 + g;
#pragma unroll
        for (int nt = 0; nt < 4; nt++) {
            int cc = n0 + wn * 32 + nt * 8 + t4 * 2;
            float2 v0 = make_float2(acc[mt][nt][0], acc[mt][nt][1]);
            float2 v1 = make_float2(acc[mt][nt][2], acc[mt][nt][3]);
            if (BIAS) {
                float2 bb = *(const float2*)(bias + cc);
                v0.x += bb.x; v0.y += bb.y; v1.x += bb.x; v1.y += bb.y;
            }
            if (RELU) {
                v0.x = fmaxf(v0.x, 0.f); v0.y = fmaxf(v0.y, 0.f);
                v1.x = fmaxf(v1.x, 0.f); v1.y = fmaxf(v1.y, 0.f);
            }
            if (RES) {
                float2 r4 = *(const float2*)(res + (size_t)r0 * N + cc);
                v0.x += r4.x; v0.y += r4.y;
                float2 r5 = *(const float2*)(res + (size_t)(r0 + 8) * N + cc);
                v1.x += r5.x; v1.y += r5.y;
            }
            if (HC) {
                __half* Ch = (__half*)Cv;
                *(__half2*)(Ch + (size_t)r0 * N + cc)       = __floats2half2_rn(v0.x, v0.y);
                *(__half2*)(Ch + (size_t)(r0 + 8) * N + cc) = __floats2half2_rn(v1.x, v1.y);
            } else {
                float* Cf = (float*)Cv;
                *(float2*)(Cf + (size_t)r0 * N + cc) = v0;
                *(float2*)(Cf + (size_t)(r0 + 8) * N + cc) = v1;
            }
        }
    }
}

template <bool BIAS, bool RELU, bool RES, bool HC>
static inline void tgemm(const __half* A, const __half* BT, const float* bias,
                         const float* res, void* C, int M, int N, int K) {
    cudaFuncSetAttribute(mm_gemm<BIAS, RELU, RES, HC>,
                         cudaFuncAttributeMaxDynamicSharedMemorySize, SMB);
    dim3 grid(N / 128, M / 64);
    mm_gemm<BIAS, RELU, RES, HC><<<grid, 256, SMB>>>(A, BT, bias, res, C, M, N, K);
}

// ---------------------------------------------------------------------------
// Weight transpose ([K,N] -> [N,K]) with fp16 conversion at the write
// ---------------------------------------------------------------------------
struct P8 { const float* p[8]; };

__global__ void trans_dd(P8 s, __half* dst) {
    __shared__ float t[32][33];
    int z = blockIdx.z;
    int kd = z / 6, i = z - kd * 6;
    const float* src = s.p[kd] + (size_t)i * 262144;
    __half* d = dst + (size_t)i * WBLK_STRIDE + (size_t)kd * 262144;
    int tx = threadIdx.x, ty = threadIdx.y;
    int x = blockIdx.x * 32 + tx;
    int y0 = blockIdx.y * 32;
#pragma unroll
    for (int r = 0; r < 32; r += 8)
        t[ty + r][tx] = src[(size_t)(y0 + ty + r) * 512 + x];
    __syncthreads();
    int x2 = y0 + tx;
    int y2 = blockIdx.x * 32;
#pragma unroll
    for (int r = 0; r < 32; r += 8)
        d[(size_t)(y2 + ty + r) * 512 + x2] = __float2half_rn(t[tx][ty + r]);
}

__global__ void trans_rc(const float* __restrict__ src, __half* __restrict__ dst,
                         int R, int C, size_t dOff) {
    __shared__ float t[32][33];
    const float* s = src + (size_t)blockIdx.z * R * C;
    __half* d = dst + (size_t)blockIdx.z * WBLK_STRIDE + dOff;
    int tx = threadIdx.x, ty = threadIdx.y;
    int x = blockIdx.x * 32 + tx;
    int y0 = blockIdx.y * 32;
#pragma unroll
    for (int r = 0; r < 32; r += 8)
        t[ty + r][tx] = s[(size_t)(y0 + ty + r) * C + x];
    __syncthreads();
    int x2 = y0 + tx;
    int y2 = blockIdx.x * 32;
#pragma unroll
    for (int r = 0; r < 32; r += 8)
        d[(size_t)(y2 + ty + r) * R + x2] = __float2half_rn(t[tx][ty + r]);
}

// fp32 -> fp16 copy (float4 granularity)
__global__ void cvt_half(const float* __restrict__ src, __half* __restrict__ dst,
                         int n4) {
    int i = blockIdx.x * 256 + threadIdx.x;
    if (i < n4) {
        float4 v = ((const float4*)src)[i];
        __half2* dp = (__half2*)dst;
        dp[i * 2]     = __floats2half2_rn(v.x, v.y);
        dp[i * 2 + 1] = __floats2half2_rn(v.z, v.w);
    }
}

// ---------------------------------------------------------------------------
// Embedding * sqrt(D) + sinusoidal positional encoding (fp32 h)
// ---------------------------------------------------------------------------
__global__ void embed_kernel(const int* __restrict__ x,
                             const float* __restrict__ emb,
                             float* __restrict__ h) {
    int n = blockIdx.x;
    int l = n & (Ll - 1);
    int tok = x[n];
    int d0 = threadIdx.x * 4;
#pragma unroll
    for (int u = 0; u < 4; u++) {
        int d = d0 + u;
        int i = (d < 256) ? d : d - 256;
        float denom = powf(10000.0f, (float)i * (1.0f / 256.0f));
        float ang = (float)l / denom;
        float pos = (d < 256) ? sinf(ang) : cosf(ang);
        h[(size_t)n * Dm + d] = emb[(size_t)tok * Dm + d] * 22.62741699796952f + pos;
    }
}

// ---------------------------------------------------------------------------
// LayerNorm (fp32 in, fp16 out — only consumed as GEMM A operand)
// ---------------------------------------------------------------------------
__global__ void ln_kernel(const float* __restrict__ x,
                          const float* __restrict__ gw,
                          const float* __restrict__ bw,
                          __half* __restrict__ y) {
    int row = blockIdx.x;
    int t = threadIdx.x;
    float4 xv = ((const float4*)(x + (size_t)row * Dm))[t];
    float s  = xv.x + xv.y + xv.z + xv.w;
    float ss = xv.x * xv.x + xv.y * xv.y + xv.z * xv.z + xv.w * xv.w;
#pragma unroll
    for (int o = 16; o > 0; o >>= 1) {
        s  += __shfl_xor_sync(0xFFFFFFFFu, s, o);
        ss += __shfl_xor_sync(0xFFFFFFFFu, ss, o);
    }
    __shared__ float sh_s[4], sh_ss[4];
    int w = t >> 5, lane = t & 31;
    if (lane == 0) { sh_s[w] = s; sh_ss[w] = ss; }
    __syncthreads();
    s  = sh_s[0] + sh_s[1] + sh_s[2] + sh_s[3];
    ss = sh_ss[0] + sh_ss[1] + sh_ss[2] + sh_ss[3];
    float mean = s * (1.0f / Dm);
    float var  = ss * (1.0f / Dm) - mean * mean;
    float inv = rsqrtf(var + 1e-6f);
    float4 gv = ((const float4*)gw)[t];
    float4 bv = ((const float4*)bw)[t];
    __half2* yp = (__half2*)(y + (size_t)row * Dm);
    yp[t * 2]     = __floats2half2_rn((xv.x - mean) * inv * gv.x + bv.x,
                                      (xv.y - mean) * inv * gv.y + bv.y);
    yp[t * 2 + 1] = __floats2half2_rn((xv.z - mean) * inv * gv.z + bv.z,
                                      (xv.w - mean) * inv * gv.w + bv.w);
}

// ---------------------------------------------------------------------------
// Fused flash-style attention: R10 structure (q-tile 128, one thread per
// query, NO intra-loop collectives -> divergence-safe), fp16 I/O, fp32 math.
// Grid (8, 8, 2) = 128 CTAs, 128 threads.
// ---------------------------------------------------------------------------
template <bool CAUSAL>
__global__ void __launch_bounds__(128)
attn_kernel(const __half* __restrict__ Q, const __half* __restrict__ K,
            const __half* __restrict__ V, __half* __restrict__ O) {
    __shared__ float Ks[64][64];
    __shared__ float Vs[64][64];
    int t = threadIdx.x;
    int qt = blockIdx.x, hh = blockIdx.y, b = blockIdx.z;
    int q = qt * 128 + t;

    const __half* qptr = Q + ((size_t)(b * Ll + q)) * Dm + hh * DH;
    float4 qv[16];
#pragma unroll
    for (int i = 0; i < 8; i++) {
        uint4 raw = ((const uint4*)qptr)[i];
        const __half2* hp = (const __half2*)&raw;
        float2 f0 = __half22float2(hp[0]), f1 = __half22float2(hp[1]);
        float2 f2 = __half22float2(hp[2]), f3 = __half22float2(hp[3]);
        qv[2 * i]     = make_float4(f0.x, f0.y, f1.x, f1.y);
        qv[2 * i + 1] = make_float4(f2.x, f2.y, f3.x, f3.y);
    }
    float4 ov[16];
#pragma unroll
    for (int d = 0; d < 16; d++) ov[d] = make_float4(0.f, 0.f, 0.f, 0.f);
    float m = -1e30f, lsum = 0.f;

    int kmax = CAUSAL ? (qt * 128 + 128) : Ll;
    for (int k0 = 0; k0 < kmax; k0 += 64) {
        // stage 64 rows x 64 halfs of K and V, converting to fp32
#pragma unroll
        for (int it = 0; it < 4; it++) {
            int idx = t + it * 128;      // 0..511 (16B segs)
            int r = idx >> 3, sg = idx & 7;
            size_t off = ((size_t)(b * Ll + k0 + r)) * Dm + hh * DH + sg * 8;
            uint4 kraw = *(const uint4*)(K + off);
            uint4 vraw = *(const uint4*)(V + off);
            const __half2* kp = (const __half2*)&kraw;
            const __half2* vp = (const __half2*)&vraw;
            float* kd = &Ks[r][sg * 8];
            float* vd = &Vs[r][sg * 8];
#pragma unroll
            for (int u = 0; u < 4; u++) {
                float2 a = __half22float2(kp[u]);
                kd[2 * u] = a.x; kd[2 * u + 1] = a.y;
                float2 bb = __half22float2(vp[u]);
                vd[2 * u] = bb.x; vd[2 * u + 1] = bb.y;
            }
        }
        __syncthreads();
        int jend = 64;
        if (CAUSAL) {
            int lim = q - k0 + 1;
            jend = lim < 64 ? (lim < 0 ? 0 : lim) : 64;
        }
        for (int j = 0; j < jend; j++) {
            const float4* kr = (const float4*)Ks[j];
            float s = 0.f;
#pragma unroll
            for (int d = 0; d < 16; d++) {
                float4 kv = kr[d];
                s += qv[d].x * kv.x + qv[d].y * kv.y + qv[d].z * kv.z + qv[d].w * kv.w;
            }
            s *= 0.125f;   // 1/sqrt(64)
            float mn = fmaxf(m, s);
            float cf = __expf(m - mn);
            float p = __expf(s - mn);
            m = mn;
            lsum = lsum * cf + p;
            const float4* vr = (const float4*)Vs[j];
#pragma unroll
            for (int d = 0; d < 16; d++) {
                float4 vvv = vr[d];
                ov[d].x = ov[d].x * cf + p * vvv.x;
                ov[d].y = ov[d].y * cf + p * vvv.y;
                ov[d].z = ov[d].z * cf + p * vvv.z;
                ov[d].w = ov[d].w * cf + p * vvv.w;
            }
        }
        __syncthreads();
    }
    float inv = 1.0f / lsum;
    __half* optr = O + ((size_t)(b * Ll + q)) * Dm + hh * DH;
#pragma unroll
    for (int i = 0; i < 8; i++) {
        uint4 o;
        __half2* op = (__half2*)&o;
        float4 r0 = ov[2 * i], r1 = ov[2 * i + 1];
        op[0] = __floats2half2_rn(r0.x * inv, r0.y * inv);
        op[1] = __floats2half2_rn(r0.z * inv, r0.w * inv);
        op[2] = __floats2half2_rn(r1.x * inv, r1.y * inv);
        op[3] = __floats2half2_rn(r1.z * inv, r1.w * inv);
        ((uint4*)optr)[i] = o;
    }
}

// ---------------------------------------------------------------------------
// kernel_launch
// ---------------------------------------------------------------------------
extern "C" void kernel_launch(void* const* d_in, const int* in_sizes, int n_in,
                              void* d_out, int out_size) {
    const int*   x     = (const int*)  d_in[0];
    const float* ctx   = (const float*)d_in[1];
    const float* emb   = (const float*)d_in[2];
    const float* wq_s  = (const float*)d_in[3];
    const float* wk_s  = (const float*)d_in[4];
    const float* wv_s  = (const float*)d_in[5];
    const float* wo_s  = (const float*)d_in[6];
    const float* wq_c  = (const float*)d_in[7];
    const float* wk_c  = (const float*)d_in[8];
    const float* wv_c  = (const float*)d_in[9];
    const float* wo_c  = (const float*)d_in[10];
    const float* w1    = (const float*)d_in[11];
    const float* b1    = (const float*)d_in[12];
    const float* w2    = (const float*)d_in[13];
    const float* b2    = (const float*)d_in[14];
    const float* ln1_g = (const float*)d_in[15];
    const float* ln1_b = (const float*)d_in[16];
    const float* ln2_g = (const float*)d_in[17];
    const float* ln2_b = (const float*)d_in[18];
    const float* ln3_g = (const float*)d_in[19];
    const float* ln3_b = (const float*)d_in[20];
    const float* lnf_g = (const float*)d_in[21];
    const float* lnf_b = (const float*)d_in[22];
    float* out = (float*)d_out;

    float *h;
    __half *y, *q, *k, *v, *o, *ff, *wt, *ctxh, *embt;
    cudaGetSymbolAddress((void**)&h,    g_h);
    cudaGetSymbolAddress((void**)&y,    g_y);
    cudaGetSymbolAddress((void**)&q,    g_q);
    cudaGetSymbolAddress((void**)&k,    g_k);
    cudaGetSymbolAddress((void**)&v,    g_v);
    cudaGetSymbolAddress((void**)&o,    g_o);
    cudaGetSymbolAddress((void**)&ff,   g_ff);
    cudaGetSymbolAddress((void**)&wt,   g_wt);
    cudaGetSymbolAddress((void**)&ctxh, g_ctx);
    cudaGetSymbolAddress((void**)&embt, g_embt);

    // ---- prep: transpose+convert weights, convert ctx and emb ----
    P8 p8;
    p8.p[0] = wq_s; p8.p[1] = wk_s; p8.p[2] = wv_s; p8.p[3] = wo_s;
    p8.p[4] = wq_c; p8.p[5] = wk_c; p8.p[6] = wv_c; p8.p[7] = wo_c;
    trans_dd<<<dim3(16, 16, 48), dim3(32, 8)>>>(p8, wt);
    trans_rc<<<dim3(64, 16, 6), dim3(32, 8)>>>(w1, wt, 512, 2048, W1T_OFF);
    trans_rc<<<dim3(16, 64, 6), dim3(32, 8)>>>(w2, wt, 2048, 512, W2T_OFF);
    cvt_half<<<(NTOK * Dm / 4 + 255) / 256, 256>>>(ctx, ctxh, NTOK * Dm / 4);
    cvt_half<<<((int)((size_t)Vv * Dm / 4) + 255) / 256, 256>>>(
        emb, embt, (int)((size_t)Vv * Dm / 4));

    embed_kernel<<<NTOK, 128>>>(x, emb, h);

    dim3 agrid(Ll / 128, Hn, Bb);

    for (int i = 0; i < NBLK; i++) {
        const __half* WT = wt + (size_t)i * WBLK_STRIDE;
        // --- self attention ---
        ln_kernel<<<NTOK, 128>>>(h, ln1_g + i * Dm, ln1_b + i * Dm, y);
        tgemm<false, false, false, true>(y, WT + 0 * 262144ull, nullptr, nullptr, q, NTOK, Dm, Dm);
        tgemm<false, false, false, true>(y, WT + 1 * 262144ull, nullptr, nullptr, k, NTOK, Dm, Dm);
        tgemm<false, false, false, true>(y, WT + 2 * 262144ull, nullptr, nullptr, v, NTOK, Dm, Dm);
        attn_kernel<true><<<agrid, 128>>>(q, k, v, o);
        tgemm<false, false, true, false>(o, WT + 3 * 262144ull, nullptr, h, h, NTOK, Dm, Dm);

        // --- cross attention ---
        ln_kernel<<<NTOK, 128>>>(h, ln2_g + i * Dm, ln2_b + i * Dm, y);
        tgemm<false, false, false, true>(y,    WT + 4 * 262144ull, nullptr, nullptr, q, NTOK, Dm, Dm);
        tgemm<false, false, false, true>(ctxh, WT + 5 * 262144ull, nullptr, nullptr, k, NTOK, Dm, Dm);
        tgemm<false, false, false, true>(ctxh, WT + 6 * 262144ull, nullptr, nullptr, v, NTOK, Dm, Dm);
        attn_kernel<false><<<agrid, 128>>>(q, k, v, o);
        tgemm<false, false, true, false>(o, WT + 7 * 262144ull, nullptr, h, h, NTOK, Dm, Dm);

        // --- FFN ---
        ln_kernel<<<NTOK, 128>>>(h, ln3_g + i * Dm, ln3_b + i * Dm, y);
        tgemm<true, true, false, true>(y,  WT + W1T_OFF, b1 + (size_t)i * Ff, nullptr, ff, NTOK, Ff, Dm);
        tgemm<true, false, true, false>(ff, WT + W2T_OFF, b2 + (size_t)i * Dm, h, h, NTOK, Dm, Ff);
    }

    // --- final LN + logits = y @ embt^T ---
    ln_kernel<<<NTOK, 128>>>(h, lnf_g, lnf_b, y);
    tgemm<false, false, false, false>(y, embt, nullptr, nullptr, out, NTOK, Vv, Dm);
}